// round 1
// baseline (speedup 1.0000x reference)
#include <cuda_runtime.h>
#include <math.h>

#define L_SEQ   2048
#define DM      1024
#define ED      2048
#define NST     16
#define DT_RANK 64

// ---------------- scratch (no allocations allowed) ----------------
__device__ float g_xz[L_SEQ * 2 * ED];       // (L, 4096): [xc | z]
__device__ float g_xc[L_SEQ * ED];           // conv+silu output
__device__ float g_dBC_part[8 * L_SEQ * 96]; // split-K partials
__device__ float g_dBC[L_SEQ * 96];          // [delta_r(64) | B(16) | C(16)]
__device__ float g_delta[L_SEQ * ED];        // softplus(...)
__device__ float g_y[L_SEQ * ED];            // (y + D*xc)*silu(z)

__device__ __forceinline__ float softplus_f(float x) {
    return x > 20.f ? x : log1pf(expf(x));
}

// ---------------- generic SGEMM: C = A(MxK) * B(NxK)^T ----------------
// A row-major lda, B row-major ldb (both K-contiguous), C row-major ldc.
// gridDim.z = split-K count (K % (z*8) == 0); each z writes C + z*M*ldc.
// EPI: 0 = plain store, 1 = softplus(acc + bias[n])
template <int EPI>
__global__ __launch_bounds__(256) void sgemm_nt(
    int M, int N, int K, int lda, int ldb, int ldc,
    const float* __restrict__ A, const float* __restrict__ B,
    float* __restrict__ C, const float* __restrict__ bias)
{
    constexpr int BM = 128, BN = 128, BK = 8, TM = 8, TN = 8;
    __shared__ float As[BK][BM];
    __shared__ float Bs[BK][BN];

    const int bm = blockIdx.y * BM;
    const int bn = blockIdx.x * BN;
    const int kc = K / gridDim.z;
    const int k0 = blockIdx.z * kc;
    C += (size_t)blockIdx.z * M * ldc;

    const int tid  = threadIdx.x;
    const int tcol = tid & 15;   // N direction
    const int trow = tid >> 4;   // M direction
    const int lrow = tid >> 1;   // load row 0..127
    const int lk   = (tid & 1) * 4;

    const bool avalid = (bm + lrow) < M;
    const bool bvalid = (bn + lrow) < N;
    const float* Ag = A + (size_t)(bm + lrow) * lda + k0 + lk;
    const float* Bg = B + (size_t)(bn + lrow) * ldb + k0 + lk;

    float acc[TM][TN];
#pragma unroll
    for (int i = 0; i < TM; i++)
#pragma unroll
        for (int j = 0; j < TN; j++) acc[i][j] = 0.f;

    for (int kb = 0; kb < kc; kb += BK) {
        float4 av = avalid ? *reinterpret_cast<const float4*>(Ag + kb)
                           : make_float4(0, 0, 0, 0);
        float4 bv = bvalid ? *reinterpret_cast<const float4*>(Bg + kb)
                           : make_float4(0, 0, 0, 0);
        As[lk + 0][lrow] = av.x; As[lk + 1][lrow] = av.y;
        As[lk + 2][lrow] = av.z; As[lk + 3][lrow] = av.w;
        Bs[lk + 0][lrow] = bv.x; Bs[lk + 1][lrow] = bv.y;
        Bs[lk + 2][lrow] = bv.z; Bs[lk + 3][lrow] = bv.w;
        __syncthreads();
#pragma unroll
        for (int k = 0; k < BK; k++) {
            float4 m0 = *reinterpret_cast<const float4*>(&As[k][trow * TM]);
            float4 m1 = *reinterpret_cast<const float4*>(&As[k][trow * TM + 4]);
            float4 n0 = *reinterpret_cast<const float4*>(&Bs[k][tcol * TN]);
            float4 n1 = *reinterpret_cast<const float4*>(&Bs[k][tcol * TN + 4]);
            float rm[8] = {m0.x, m0.y, m0.z, m0.w, m1.x, m1.y, m1.z, m1.w};
            float rn[8] = {n0.x, n0.y, n0.z, n0.w, n1.x, n1.y, n1.z, n1.w};
#pragma unroll
            for (int i = 0; i < TM; i++)
#pragma unroll
                for (int j = 0; j < TN; j++)
                    acc[i][j] = fmaf(rm[i], rn[j], acc[i][j]);
        }
        __syncthreads();
    }

#pragma unroll
    for (int i = 0; i < TM; i++) {
        int m = bm + trow * TM + i;
        if (m >= M) continue;
#pragma unroll
        for (int j = 0; j < TN; j += 4) {
            int n = bn + tcol * TN + j;
            if (n < N) {  // all N are multiples of 4, vector fully valid
                float4 v = make_float4(acc[i][j], acc[i][j + 1],
                                       acc[i][j + 2], acc[i][j + 3]);
                if (EPI == 1) {
                    v.x = softplus_f(v.x + bias[n + 0]);
                    v.y = softplus_f(v.y + bias[n + 1]);
                    v.z = softplus_f(v.z + bias[n + 2]);
                    v.w = softplus_f(v.w + bias[n + 3]);
                }
                *reinterpret_cast<float4*>(&C[(size_t)m * ldc + n]) = v;
            }
        }
    }
}

// ---------------- depthwise causal conv (K=4) + bias + SiLU ----------------
__global__ __launch_bounds__(256) void conv_silu_kernel(
    const float* __restrict__ xz, const float* __restrict__ cw,
    const float* __restrict__ cb, float* __restrict__ xc)
{
    int idx = blockIdx.x * 256 + threadIdx.x;
    if (idx >= L_SEQ * ED) return;
    int e = idx & (ED - 1);
    int l = idx >> 11;
    float acc = cb[e];
#pragma unroll
    for (int k = 0; k < 4; k++) {
        int ll = l - 3 + k;
        if (ll >= 0)
            acc = fmaf(xz[(size_t)ll * (2 * ED) + e], cw[e * 4 + k], acc);
    }
    float s = acc / (1.f + __expf(-acc));  // silu
    xc[(size_t)l * ED + e] = s;
}

// ---------------- split-K reduction (fixed order -> deterministic) ----------
__global__ __launch_bounds__(256) void reduce8_kernel(
    const float* __restrict__ part, float* __restrict__ out, int total)
{
    int i = blockIdx.x * 256 + threadIdx.x;
    if (i >= total) return;
    float s = 0.f;
#pragma unroll
    for (int z = 0; z < 8; z++) s += part[(size_t)z * total + i];
    out[i] = s;
}

// ---------------- momentum SSM scan ----------------
// thread: n = tid&15, e_local = tid>>4; block covers 16 e-channels.
// chunked shared staging: 64 timesteps per chunk.
__global__ __launch_bounds__(256) void scan_kernel(
    const float* __restrict__ delta, const float* __restrict__ dBC,
    const float* __restrict__ xc, const float* __restrict__ xz,
    const float* __restrict__ A_log, const float* __restrict__ Dp,
    float* __restrict__ y)
{
    constexpr int ET = 16, CH = 64;
    __shared__ float s_d[CH][ET];
    __shared__ float s_x[CH][ET];
    __shared__ float s_z[CH][ET];
    __shared__ float s_B[CH][NST];
    __shared__ float s_C[CH][NST];

    const int tid = threadIdx.x;
    const int n  = tid & 15;
    const int el = tid >> 4;
    const int e0 = blockIdx.x * ET;
    const int e  = e0 + el;

    const float Acoef = -__expf(A_log[e * NST + n]);
    const float Dv    = Dp[e];

    float h = 0.f, v = 0.f;

    for (int c0 = 0; c0 < L_SEQ; c0 += CH) {
        // cooperative stage: delta/xc/z per (t, e_local), B/C per (t, n)
        for (int i = tid; i < CH * ET; i += 256) {
            int ll = i >> 4, ee = i & 15;
            size_t gl = (size_t)(c0 + ll);
            s_d[ll][ee] = delta[gl * ED + e0 + ee];
            s_x[ll][ee] = xc[gl * ED + e0 + ee];
            s_z[ll][ee] = xz[gl * (2 * ED) + ED + e0 + ee];
        }
        for (int i = tid; i < CH * NST; i += 256) {
            int ll = i >> 4, nn = i & 15;
            size_t gl = (size_t)(c0 + ll);
            s_B[ll][nn] = dBC[gl * 96 + 64 + nn];
            s_C[ll][nn] = dBC[gl * 96 + 80 + nn];
        }
        __syncthreads();

#pragma unroll 4
        for (int t = 0; t < CH; t++) {
            float d  = s_d[t][el];
            float xv = s_x[t][el];
            float u  = d * s_B[t][n] * xv;        // ALPHA = 1
            float dA = __expf(d * Acoef);
            v = fmaf(0.6f, v, u);                 // BETA = 0.6
            h = fmaf(dA, h, v);
            float p = h * s_C[t][n];
            p += __shfl_xor_sync(0xffffffffu, p, 1, 32);
            p += __shfl_xor_sync(0xffffffffu, p, 2, 32);
            p += __shfl_xor_sync(0xffffffffu, p, 4, 32);
            p += __shfl_xor_sync(0xffffffffu, p, 8, 32);
            if (n == 0) {
                float zz = s_z[t][el];
                float sz = zz / (1.f + __expf(-zz));
                y[(size_t)(c0 + t) * ED + e] = (p + Dv * xv) * sz;
            }
        }
        __syncthreads();
    }
}

// ---------------- launch ----------------
extern "C" void kernel_launch(void* const* d_in, const int* in_sizes, int n_in,
                              void* d_out, int out_size)
{
    const float* x      = (const float*)d_in[0];
    const float* W_in   = (const float*)d_in[1];
    const float* conv_w = (const float*)d_in[2];
    const float* conv_b = (const float*)d_in[3];
    const float* W_x    = (const float*)d_in[4];
    const float* W_dt   = (const float*)d_in[5];
    const float* b_dt   = (const float*)d_in[6];
    const float* A_log  = (const float*)d_in[7];
    const float* Dp     = (const float*)d_in[8];
    const float* W_out  = (const float*)d_in[9];
    float* out = (float*)d_out;

    float *xz, *xc, *part, *dBC, *delta, *y;
    cudaGetSymbolAddress((void**)&xz,    g_xz);
    cudaGetSymbolAddress((void**)&xc,    g_xc);
    cudaGetSymbolAddress((void**)&part,  g_dBC_part);
    cudaGetSymbolAddress((void**)&dBC,   g_dBC);
    cudaGetSymbolAddress((void**)&delta, g_delta);
    cudaGetSymbolAddress((void**)&y,     g_y);

    // 1) xz = x @ W_in^T                         (2048 x 4096 x 1024)
    sgemm_nt<0><<<dim3(2 * ED / 128, L_SEQ / 128, 1), 256>>>(
        L_SEQ, 2 * ED, DM, DM, DM, 2 * ED, x, W_in, xz, nullptr);

    // 2) depthwise conv + bias + silu -> xc
    conv_silu_kernel<<<(L_SEQ * ED) / 256, 256>>>(xz, conv_w, conv_b, xc);

    // 3) dBC = xc @ W_x^T  (split-K x8 for parallelism, then reduce)
    sgemm_nt<0><<<dim3(1, L_SEQ / 128, 8), 256>>>(
        L_SEQ, 96, ED, ED, ED, 96, xc, W_x, part, nullptr);
    reduce8_kernel<<<(L_SEQ * 96 + 255) / 256, 256>>>(part, dBC, L_SEQ * 96);

    // 4) delta = softplus(dBC[:, :64] @ W_dt^T + b_dt)   (2048 x 2048 x 64)
    sgemm_nt<1><<<dim3(ED / 128, L_SEQ / 128, 1), 256>>>(
        L_SEQ, ED, DT_RANK, 96, DT_RANK, ED, dBC, W_dt, delta, b_dt);

    // 5) momentum SSM scan -> y_final = (y_ssm + D*xc) * silu(z)
    scan_kernel<<<ED / 16, 256>>>(delta, dBC, xc, xz, A_log, Dp, y);

    // 6) out = y_final @ W_out^T                 (2048 x 1024 x 2048)
    sgemm_nt<0><<<dim3(DM / 128, L_SEQ / 128, 1), 256>>>(
        L_SEQ, DM, ED, ED, ED, DM, y, W_out, out, nullptr);
}

// round 3
// speedup vs baseline: 1.6871x; 1.6871x over previous
#include <cuda_runtime.h>
#include <cuda_bf16.h>
#include <math.h>
#include <stdint.h>

#define L_SEQ   2048
#define DM      1024
#define ED      2048
#define NST     16
#define DT_RANK 64

// ---------------- scratch (no allocations allowed) ----------------
__device__ float g_xz[L_SEQ * 2 * ED];       // (L, 4096): [xc | z]
__device__ float g_xc[L_SEQ * ED];           // conv+silu output
__device__ float g_dBC_part[8 * L_SEQ * 96]; // split-K partials
__device__ float g_dBC[L_SEQ * 96];          // [delta_r(64) | B(16) | C(16)]
__device__ float g_delta[L_SEQ * ED];        // softplus(...)
__device__ float g_y[L_SEQ * ED];            // (y + D*xc)*silu(z)

__device__ __forceinline__ float softplus_f(float x) {
    return x > 20.f ? x : log1pf(expf(x));
}

__device__ __forceinline__ uint32_t smem_u32(const void* p) {
    uint32_t a;
    asm("{ .reg .u64 t; cvta.to.shared.u64 t, %1; cvt.u32.u64 %0, t; }"
        : "=r"(a) : "l"(p));
    return a;
}

__device__ __forceinline__ void ldsm4(uint32_t* r, uint32_t a) {
    asm volatile("ldmatrix.sync.aligned.m8n8.x4.shared.b16 {%0,%1,%2,%3}, [%4];"
                 : "=r"(r[0]), "=r"(r[1]), "=r"(r[2]), "=r"(r[3]) : "r"(a));
}

__device__ __forceinline__ void mma_bf16(float* c, const uint32_t* a,
                                         const uint32_t* b) {
    asm volatile(
        "mma.sync.aligned.m16n8k16.row.col.f32.bf16.bf16.f32 "
        "{%0,%1,%2,%3}, {%4,%5,%6,%7}, {%8,%9}, {%0,%1,%2,%3};"
        : "+f"(c[0]), "+f"(c[1]), "+f"(c[2]), "+f"(c[3])
        : "r"(a[0]), "r"(a[1]), "r"(a[2]), "r"(a[3]), "r"(b[0]), "r"(b[1]));
}

__device__ __forceinline__ uint32_t pack_bf16(__nv_bfloat16 x, __nv_bfloat16 y) {
    __nv_bfloat162 t = __halves2bfloat162(x, y);
    return *reinterpret_cast<uint32_t*>(&t);
}

#define SW64(x) ((x) ^ (((x) >> 3) & 0x30))

// ======== tensor-core GEMM via mma.sync: C(MxN) = A(MxK) @ B(NxK)^T =========
// fp32 in/out; bf16 hi/lo split (3 mma products) for fp32-class accuracy.
// BM=BN=128, BK=32, 256 threads (8 warps as 2x4, warp tile 64x32).
// smem stage: Ah(8K) Al(8K) Bh(8K) Bl(8K) = 32KB, double buffered = 64KB.
#define GM_STAGE 32768
#define GM_A_HI  0
#define GM_A_LO  8192
#define GM_B_HI  16384
#define GM_B_LO  24576
#define GM_SMEM  (2 * GM_STAGE)

__global__ __launch_bounds__(256) void gemm_mma(
    int M, int N, int K, int lda, int ldb, int ldc,
    const float* __restrict__ A, const float* __restrict__ B,
    float* __restrict__ C)
{
    extern __shared__ char smem[];
    const uint32_t sb = smem_u32(smem);
    const int tid  = threadIdx.x;
    const int wid  = tid >> 5;
    const int lane = tid & 31;
    const int bm = blockIdx.y * 128;
    const int bn = blockIdx.x * 128;
    const int wm = (wid >> 2) * 64;
    const int wn = (wid & 3) * 32;

    float acc[4][4][4];
#pragma unroll
    for (int i = 0; i < 4; i++)
#pragma unroll
        for (int j = 0; j < 4; j++)
#pragma unroll
            for (int k = 0; k < 4; k++) acc[i][j][k] = 0.f;

    float4 ra[4], rb[4];
    const int lrow = tid >> 3;          // base row (each i adds 32)
    const int lcq  = tid & 7;           // float4 chunk within row

#define GM_LOAD(c) do {                                                        \
    int _k0 = (c) * 32;                                                        \
    _Pragma("unroll")                                                          \
    for (int i = 0; i < 4; i++) {                                              \
        int row = lrow + i * 32;                                               \
        ra[i] = *reinterpret_cast<const float4*>(                              \
            A + (size_t)(bm + row) * lda + _k0 + lcq * 4);                     \
        rb[i] = *reinterpret_cast<const float4*>(                              \
            B + (size_t)(bn + row) * ldb + _k0 + lcq * 4);                     \
    } } while (0)

#define GM_SPLIT_STS(v, off_hi, off_lo, sw) do {                               \
    __nv_bfloat16 h0 = __float2bfloat16((v).x);                                \
    __nv_bfloat16 h1 = __float2bfloat16((v).y);                                \
    __nv_bfloat16 h2 = __float2bfloat16((v).z);                                \
    __nv_bfloat16 h3 = __float2bfloat16((v).w);                                \
    __nv_bfloat16 l0 = __float2bfloat16((v).x - __bfloat162float(h0));         \
    __nv_bfloat16 l1 = __float2bfloat16((v).y - __bfloat162float(h1));         \
    __nv_bfloat16 l2 = __float2bfloat16((v).z - __bfloat162float(h2));         \
    __nv_bfloat16 l3 = __float2bfloat16((v).w - __bfloat162float(h3));         \
    uint32_t hA = pack_bf16(h0, h1), hB = pack_bf16(h2, h3);                   \
    uint32_t lA = pack_bf16(l0, l1), lB = pack_bf16(l2, l3);                   \
    asm volatile("st.shared.v2.b32 [%0], {%1, %2};"                            \
                 :: "r"((off_hi) + (sw)), "r"(hA), "r"(hB) : "memory");        \
    asm volatile("st.shared.v2.b32 [%0], {%1, %2};"                            \
                 :: "r"((off_lo) + (sw)), "r"(lA), "r"(lB) : "memory");        \
    } while (0)

#define GM_STS(stage) do {                                                     \
    uint32_t _b = sb + (stage) * GM_STAGE;                                     \
    _Pragma("unroll")                                                          \
    for (int i = 0; i < 4; i++) {                                              \
        int row = lrow + i * 32;                                               \
        uint32_t off = (uint32_t)(row * 64 + lcq * 8);                         \
        uint32_t sw = SW64(off);                                               \
        GM_SPLIT_STS(ra[i], _b + GM_A_HI, _b + GM_A_LO, sw);                   \
        GM_SPLIT_STS(rb[i], _b + GM_B_HI, _b + GM_B_LO, sw);                   \
    } } while (0)

    // prologue
    GM_LOAD(0);
    GM_STS(0);
    __syncthreads();

    const int NC = K >> 5;
    for (int c = 0; c < NC; c++) {
        if (c + 1 < NC) GM_LOAD(c + 1);

        // ---- compute on stage c&1 ----
        {
            uint32_t base = sb + (c & 1) * GM_STAGE;
            const int arow = (lane & 7) + ((lane >> 3) & 1) * 8;
            const int brow = (lane & 7) + ((lane >> 4) & 1) * 8;
#pragma unroll
            for (int ks = 0; ks < 2; ks++) {
                uint32_t aH[4][4], aL[4][4], bH[2][4], bL[2][4];
                const int akb = ks * 32 + ((lane >> 4) & 1) * 16;
                const int bkb = ks * 32 + ((lane >> 3) & 1) * 16;
#pragma unroll
                for (int mt = 0; mt < 4; mt++) {
                    uint32_t off = (uint32_t)((wm + mt * 16 + arow) * 64 + akb);
                    off = SW64(off);
                    ldsm4(aH[mt], base + GM_A_HI + off);
                    ldsm4(aL[mt], base + GM_A_LO + off);
                }
#pragma unroll
                for (int nt2 = 0; nt2 < 2; nt2++) {
                    uint32_t off = (uint32_t)((wn + nt2 * 16 + brow) * 64 + bkb);
                    off = SW64(off);
                    ldsm4(bH[nt2], base + GM_B_HI + off);
                    ldsm4(bL[nt2], base + GM_B_LO + off);
                }
#pragma unroll
                for (int mt = 0; mt < 4; mt++)
#pragma unroll
                    for (int nt = 0; nt < 4; nt++) {
                        const uint32_t* bh = &bH[nt >> 1][(nt & 1) * 2];
                        const uint32_t* bl = &bL[nt >> 1][(nt & 1) * 2];
                        mma_bf16(acc[mt][nt], aH[mt], bh);
                        mma_bf16(acc[mt][nt], aH[mt], bl);
                        mma_bf16(acc[mt][nt], aL[mt], bh);
                    }
            }
        }

        if (c + 1 < NC) GM_STS((c + 1) & 1);
        __syncthreads();
    }

    // epilogue
    const int g = lane >> 2, tig = lane & 3;
#pragma unroll
    for (int mt = 0; mt < 4; mt++)
#pragma unroll
        for (int nt = 0; nt < 4; nt++) {
            size_t r = (size_t)(bm + wm + mt * 16 + g);
            int cc = bn + wn + nt * 8 + tig * 2;
            *reinterpret_cast<float2*>(&C[r * ldc + cc]) =
                make_float2(acc[mt][nt][0], acc[mt][nt][1]);
            *reinterpret_cast<float2*>(&C[(r + 8) * ldc + cc]) =
                make_float2(acc[mt][nt][2], acc[mt][nt][3]);
        }
}

// ---------------- generic FFMA SGEMM (small GEMMs) ----------------
template <int EPI>
__global__ __launch_bounds__(256) void sgemm_nt(
    int M, int N, int K, int lda, int ldb, int ldc,
    const float* __restrict__ A, const float* __restrict__ B,
    float* __restrict__ C, const float* __restrict__ bias)
{
    constexpr int BM = 128, BN = 128, BK = 8, TM = 8, TN = 8;
    __shared__ float As[BK][BM];
    __shared__ float Bs[BK][BN];

    const int bm = blockIdx.y * BM;
    const int bn = blockIdx.x * BN;
    const int kc = K / gridDim.z;
    const int k0 = blockIdx.z * kc;
    C += (size_t)blockIdx.z * M * ldc;

    const int tid  = threadIdx.x;
    const int tcol = tid & 15;
    const int trow = tid >> 4;
    const int lrow = tid >> 1;
    const int lk   = (tid & 1) * 4;

    const bool avalid = (bm + lrow) < M;
    const bool bvalid = (bn + lrow) < N;
    const float* Ag = A + (size_t)(bm + lrow) * lda + k0 + lk;
    const float* Bg = B + (size_t)(bn + lrow) * ldb + k0 + lk;

    float acc[TM][TN];
#pragma unroll
    for (int i = 0; i < TM; i++)
#pragma unroll
        for (int j = 0; j < TN; j++) acc[i][j] = 0.f;

    for (int kb = 0; kb < kc; kb += BK) {
        float4 av = avalid ? *reinterpret_cast<const float4*>(Ag + kb)
                           : make_float4(0, 0, 0, 0);
        float4 bv = bvalid ? *reinterpret_cast<const float4*>(Bg + kb)
                           : make_float4(0, 0, 0, 0);
        As[lk + 0][lrow] = av.x; As[lk + 1][lrow] = av.y;
        As[lk + 2][lrow] = av.z; As[lk + 3][lrow] = av.w;
        Bs[lk + 0][lrow] = bv.x; Bs[lk + 1][lrow] = bv.y;
        Bs[lk + 2][lrow] = bv.z; Bs[lk + 3][lrow] = bv.w;
        __syncthreads();
#pragma unroll
        for (int k = 0; k < BK; k++) {
            float4 m0 = *reinterpret_cast<const float4*>(&As[k][trow * TM]);
            float4 m1 = *reinterpret_cast<const float4*>(&As[k][trow * TM + 4]);
            float4 n0 = *reinterpret_cast<const float4*>(&Bs[k][tcol * TN]);
            float4 n1 = *reinterpret_cast<const float4*>(&Bs[k][tcol * TN + 4]);
            float rm[8] = {m0.x, m0.y, m0.z, m0.w, m1.x, m1.y, m1.z, m1.w};
            float rn[8] = {n0.x, n0.y, n0.z, n0.w, n1.x, n1.y, n1.z, n1.w};
#pragma unroll
            for (int i = 0; i < TM; i++)
#pragma unroll
                for (int j = 0; j < TN; j++)
                    acc[i][j] = fmaf(rm[i], rn[j], acc[i][j]);
        }
        __syncthreads();
    }

#pragma unroll
    for (int i = 0; i < TM; i++) {
        int m = bm + trow * TM + i;
        if (m >= M) continue;
#pragma unroll
        for (int j = 0; j < TN; j += 4) {
            int n = bn + tcol * TN + j;
            if (n < N) {
                float4 v = make_float4(acc[i][j], acc[i][j + 1],
                                       acc[i][j + 2], acc[i][j + 3]);
                if (EPI == 1) {
                    v.x = softplus_f(v.x + bias[n + 0]);
                    v.y = softplus_f(v.y + bias[n + 1]);
                    v.z = softplus_f(v.z + bias[n + 2]);
                    v.w = softplus_f(v.w + bias[n + 3]);
                }
                *reinterpret_cast<float4*>(&C[(size_t)m * ldc + n]) = v;
            }
        }
    }
}

// ---------------- depthwise causal conv (K=4) + bias + SiLU ----------------
__global__ __launch_bounds__(256) void conv_silu_kernel(
    const float* __restrict__ xz, const float* __restrict__ cw,
    const float* __restrict__ cb, float* __restrict__ xc)
{
    int idx = blockIdx.x * 256 + threadIdx.x;
    if (idx >= L_SEQ * ED) return;
    int e = idx & (ED - 1);
    int l = idx >> 11;
    float acc = cb[e];
#pragma unroll
    for (int k = 0; k < 4; k++) {
        int ll = l - 3 + k;
        if (ll >= 0)
            acc = fmaf(xz[(size_t)ll * (2 * ED) + e], cw[e * 4 + k], acc);
    }
    float s = acc / (1.f + __expf(-acc));
    xc[(size_t)l * ED + e] = s;
}

// ---------------- split-K reduction (fixed order -> deterministic) ----------
__global__ __launch_bounds__(256) void reduce8_kernel(
    const float* __restrict__ part, float* __restrict__ out, int total)
{
    int i = blockIdx.x * 256 + threadIdx.x;
    if (i >= total) return;
    float s = 0.f;
#pragma unroll
    for (int z = 0; z < 8; z++) s += part[(size_t)z * total + i];
    out[i] = s;
}

// ---------------- momentum SSM scan ----------------
__global__ __launch_bounds__(256) void scan_kernel(
    const float* __restrict__ delta, const float* __restrict__ dBC,
    const float* __restrict__ xc, const float* __restrict__ xz,
    const float* __restrict__ A_log, const float* __restrict__ Dp,
    float* __restrict__ y)
{
    constexpr int ET = 16, CH = 64;
    __shared__ float s_d[CH][ET];
    __shared__ float s_x[CH][ET];
    __shared__ float s_z[CH][ET];
    __shared__ float s_B[CH][NST];
    __shared__ float s_C[CH][NST];

    const int tid = threadIdx.x;
    const int n  = tid & 15;
    const int el = tid >> 4;
    const int e0 = blockIdx.x * ET;
    const int e  = e0 + el;

    const float Acoef = -__expf(A_log[e * NST + n]);
    const float Dv    = Dp[e];

    float h = 0.f, v = 0.f;

    for (int c0 = 0; c0 < L_SEQ; c0 += CH) {
        for (int i = tid; i < CH * ET; i += 256) {
            int ll = i >> 4, ee = i & 15;
            size_t gl = (size_t)(c0 + ll);
            s_d[ll][ee] = delta[gl * ED + e0 + ee];
            s_x[ll][ee] = xc[gl * ED + e0 + ee];
            s_z[ll][ee] = xz[gl * (2 * ED) + ED + e0 + ee];
        }
        for (int i = tid; i < CH * NST; i += 256) {
            int ll = i >> 4, nn = i & 15;
            size_t gl = (size_t)(c0 + ll);
            s_B[ll][nn] = dBC[gl * 96 + 64 + nn];
            s_C[ll][nn] = dBC[gl * 96 + 80 + nn];
        }
        __syncthreads();

#pragma unroll 4
        for (int t = 0; t < CH; t++) {
            float d  = s_d[t][el];
            float xv = s_x[t][el];
            float u  = d * s_B[t][n] * xv;
            float dA = __expf(d * Acoef);
            v = fmaf(0.6f, v, u);
            h = fmaf(dA, h, v);
            float p = h * s_C[t][n];
            p += __shfl_xor_sync(0xffffffffu, p, 1, 32);
            p += __shfl_xor_sync(0xffffffffu, p, 2, 32);
            p += __shfl_xor_sync(0xffffffffu, p, 4, 32);
            p += __shfl_xor_sync(0xffffffffu, p, 8, 32);
            if (n == 0) {
                float zz = s_z[t][el];
                float sz = zz / (1.f + __expf(-zz));
                y[(size_t)(c0 + t) * ED + e] = (p + Dv * xv) * sz;
            }
        }
        __syncthreads();
    }
}

// ---------------- launch ----------------
extern "C" void kernel_launch(void* const* d_in, const int* in_sizes, int n_in,
                              void* d_out, int out_size)
{
    const float* x      = (const float*)d_in[0];
    const float* W_in   = (const float*)d_in[1];
    const float* conv_w = (const float*)d_in[2];
    const float* conv_b = (const float*)d_in[3];
    const float* W_x    = (const float*)d_in[4];
    const float* W_dt   = (const float*)d_in[5];
    const float* b_dt   = (const float*)d_in[6];
    const float* A_log  = (const float*)d_in[7];
    const float* Dp     = (const float*)d_in[8];
    const float* W_out  = (const float*)d_in[9];
    float* out = (float*)d_out;

    float *xz, *xc, *part, *dBC, *delta, *y;
    cudaGetSymbolAddress((void**)&xz,    g_xz);
    cudaGetSymbolAddress((void**)&xc,    g_xc);
    cudaGetSymbolAddress((void**)&part,  g_dBC_part);
    cudaGetSymbolAddress((void**)&dBC,   g_dBC);
    cudaGetSymbolAddress((void**)&delta, g_delta);
    cudaGetSymbolAddress((void**)&y,     g_y);

    cudaFuncSetAttribute(gemm_mma, cudaFuncAttributeMaxDynamicSharedMemorySize,
                         GM_SMEM);

    // 1) xz = x @ W_in^T                         (2048 x 4096 x 1024) mma
    gemm_mma<<<dim3(2 * ED / 128, L_SEQ / 128), 256, GM_SMEM>>>(
        L_SEQ, 2 * ED, DM, DM, DM, 2 * ED, x, W_in, xz);

    // 2) depthwise conv + bias + silu -> xc
    conv_silu_kernel<<<(L_SEQ * ED) / 256, 256>>>(xz, conv_w, conv_b, xc);

    // 3) dBC = xc @ W_x^T  (split-K x8 + deterministic reduce)
    sgemm_nt<0><<<dim3(1, L_SEQ / 128, 8), 256>>>(
        L_SEQ, 96, ED, ED, ED, 96, xc, W_x, part, nullptr);
    reduce8_kernel<<<(L_SEQ * 96 + 255) / 256, 256>>>(part, dBC, L_SEQ * 96);

    // 4) delta = softplus(dBC[:, :64] @ W_dt^T + b_dt)   (2048 x 2048 x 64)
    sgemm_nt<1><<<dim3(ED / 128, L_SEQ / 128, 1), 256>>>(
        L_SEQ, ED, DT_RANK, 96, DT_RANK, ED, dBC, W_dt, delta, b_dt);

    // 5) momentum SSM scan -> y_final = (y_ssm + D*xc) * silu(z)
    scan_kernel<<<ED / 16, 256>>>(delta, dBC, xc, xz, A_log, Dp, y);

    // 6) out = y_final @ W_out^T                 (2048 x 1024 x 2048) mma
    gemm_mma<<<dim3(DM / 128, L_SEQ / 128), 256, GM_SMEM>>>(
        L_SEQ, DM, ED, ED, ED, DM, y, W_out, out);
}